// round 7
// baseline (speedup 1.0000x reference)
#include <cuda_runtime.h>
#include <cstdint>

// Problem shape (fixed)
#define Bn   16
#define Tn   8192
#define Cn   128
#define NCH  128          // chunks along T
#define CT   64           // timesteps per chunk
#define NW   8            // warps per block (each warp = one 8-step time slice)
#define HT   8            // timesteps per warp
#define LNS  32           // lanes; lane owns 4 channels (float4)

// ---------------- device scratch (static; no allocations) ----------------
__device__ float4 g_aggx[Bn * NCH * LNS];   // per-chunk local sum of x
__device__ float4 g_aggn[Bn * NCH * LNS];   // per-chunk local observed count
__device__ float4 g_aggq[Bn * NCH * LNS];   // per-chunk local sum of term^2
__device__ unsigned g_flags[2 * Bn * NCH];

// ---------------- helpers ----------------
__device__ __forceinline__ unsigned ld_acquire(const unsigned* p) {
    unsigned v;
    asm volatile("ld.acquire.gpu.u32 %0, [%1];" : "=r"(v) : "l"(p) : "memory");
    return v;
}
__device__ __forceinline__ void st_release(unsigned* p, unsigned v) {
    asm volatile("st.release.gpu.u32 [%0], %1;" :: "l"(p), "r"(v) : "memory");
}
__device__ __forceinline__ float frcp(float x) {
    float r; asm("rcp.approx.ftz.f32 %0, %1;" : "=f"(r) : "f"(x)); return r;
}
__device__ __forceinline__ float frsq(float x) {
    float r; asm("rsqrt.approx.ftz.f32 %0, %1;" : "=f"(r) : "f"(x)); return r;
}
__device__ __forceinline__ void add4(float4& a, const float4& b) {
    a.x += b.x; a.y += b.y; a.z += b.z; a.w += b.w;
}

__global__ void revin_init_flags() {
    int i = blockIdx.x * blockDim.x + threadIdx.x;
    if (i < 2 * Bn * NCH) g_flags[i] = 0u;
}

// One channel's step for P2 (accumulate lsq)
#define P2_STEP(F, BIT)                                              \
    {                                                                \
        float nm = (float)((mreg >> (BIT)) & 1u);                    \
        sx.F += xv.F; sn.F += nm;                                    \
        float nn = (sn.F == 0.f) ? 1.f : sn.F;                       \
        float mean = sx.F * frcp(nn);                                \
        float d = (xv.F - mean) * nm;                                \
        lsq.F = fmaf(d, d, lsq.F);                                   \
    }

// One channel's step for P3 (produce output)
#define P3_STEP(F, BIT)                                              \
    {                                                                \
        float nm = (float)((mreg >> (BIT)) & 1u);                    \
        sx.F += xv.F; sn.F += nm;                                    \
        float nn = (sn.F == 0.f) ? 1.f : sn.F;                       \
        float rcpn = frcp(nn);                                       \
        float mean = sx.F * rcpn;                                    \
        float d = (xv.F - mean) * nm;                                \
        ssq.F = fmaf(d, d, ssq.F);                                   \
        float var = ssq.F * rcpn;                                    \
        float inv = (var > 1e-10f) ? frsq(var) : 1.f;                \
        float ov = (xv.F - mean) * inv;                              \
        o.F = fminf(fmaxf(ov, -100.f), 100.f);                       \
    }

// ---------------- main kernel ----------------
// grid = (NCH, Bn), block = 256 threads (8 warps x 32 lanes).
__global__ __launch_bounds__(256, 3) void revin_kernel(
    const float* __restrict__ x,
    const float* __restrict__ mask,
    float* __restrict__ out)
{
    __shared__ float4 s_a[NW][LNS];
    __shared__ float4 s_b[NW][LNS];

    const int tid = threadIdx.x;
    const int w = tid >> 5;          // time slice
    const int l = tid & 31;          // channel quad
    const int k = blockIdx.x;        // chunk along T
    const int b = blockIdx.y;        // batch
    const int bN = b * NCH;

    const size_t base = (size_t)((b * Tn + k * CT + w * HT) * Cn) + 4 * l;
    const float4* __restrict__ px = (const float4*)(x    + base);
    const float4* __restrict__ pm = (const float4*)(mask + base);
    float4*       __restrict__ po = (float4*)(out + base);
    // per-timestep stride = Cn/4 = 32 float4

    unsigned* flagsA = g_flags + bN;
    unsigned* flagsB = g_flags + Bn * NCH + bN;
    const int ai = (bN + k) * LNS + l;

    // ---------------- Phase 1: single gmem read; x -> regs, mask -> bits ----
    float4 xr[HT];
    unsigned mreg = 0u;   // bit (4t+c) set => observed channel c at local step t
    #pragma unroll
    for (int t = 0; t < HT; ++t) {
        xr[t] = px[t * 32];
        float4 mv = pm[t * 32];
        mreg |= ((unsigned)(mv.x == 0.f)) << (4 * t);
        mreg |= ((unsigned)(mv.y == 0.f)) << (4 * t + 1);
        mreg |= ((unsigned)(mv.z == 0.f)) << (4 * t + 2);
        mreg |= ((unsigned)(mv.w == 0.f)) << (4 * t + 3);
    }
    float4 Lx = make_float4(0.f, 0.f, 0.f, 0.f);
    #pragma unroll
    for (int t = 0; t < HT; ++t) add4(Lx, xr[t]);
    float4 Ln = make_float4((float)__popc(mreg & 0x11111111u),
                            (float)__popc(mreg & 0x22222222u),
                            (float)__popc(mreg & 0x44444444u),
                            (float)__popc(mreg & 0x88888888u));

    // intra-block exclusive scan over the 8 time slices
    s_a[w][l] = Lx;
    s_b[w][l] = Ln;
    __syncthreads();                                        // S1
    float4 exx = make_float4(0.f, 0.f, 0.f, 0.f);
    float4 exn = make_float4(0.f, 0.f, 0.f, 0.f);
    #pragma unroll
    for (int j = 0; j < NW; ++j) {
        if (j < w) { add4(exx, s_a[j][l]); add4(exn, s_b[j][l]); }
    }
    if (w == NW - 1) {   // last slice holds chunk total = prefix + own
        float4 tx = exx, tn = exn;
        add4(tx, Lx); add4(tn, Ln);
        g_aggx[ai] = tx;
        g_aggn[ai] = tn;
    }
    __syncthreads();                                        // S2
    if (tid == 0) { __threadfence(); st_release(&flagsA[k], 1u); }

    // ---------------- Lookback 1: parallel wait, warp-strided sum ----------
    if (tid < k) {
        while (ld_acquire(&flagsA[tid]) == 0u) __nanosleep(40);
    }
    __syncthreads();                                        // S3
    {
        float4 ax = make_float4(0.f, 0.f, 0.f, 0.f);
        float4 an = make_float4(0.f, 0.f, 0.f, 0.f);
        for (int j = w; j < k; j += NW) {
            add4(ax, g_aggx[(bN + j) * LNS + l]);
            add4(an, g_aggn[(bN + j) * LNS + l]);
        }
        s_a[w][l] = ax;
        s_b[w][l] = an;
    }
    __syncthreads();                                        // S4
    #pragma unroll
    for (int j = 0; j < NW; ++j) { add4(exx, s_a[j][l]); add4(exn, s_b[j][l]); }
    // exx/exn now = this thread's exact exclusive (Sx, Sn) seed

    // ---------------- Phase 2: running mean; local term^2 (regs only) ------
    float4 sx = exx, sn = exn;
    float4 lsq = make_float4(0.f, 0.f, 0.f, 0.f);
    #pragma unroll
    for (int t = 0; t < HT; ++t) {
        float4 xv = xr[t];
        P2_STEP(x, 4 * t)
        P2_STEP(y, 4 * t + 1)
        P2_STEP(z, 4 * t + 2)
        P2_STEP(w, 4 * t + 3)
    }

    __syncthreads();                                        // S5 (s_a reuse safe)
    s_a[w][l] = lsq;
    __syncthreads();                                        // S6
    float4 exq = make_float4(0.f, 0.f, 0.f, 0.f);
    #pragma unroll
    for (int j = 0; j < NW; ++j) {
        if (j < w) add4(exq, s_a[j][l]);
    }
    if (w == NW - 1) {
        float4 tq = exq; add4(tq, lsq);
        g_aggq[ai] = tq;
    }
    __syncthreads();                                        // S7
    if (tid == 0) { __threadfence(); st_release(&flagsB[k], 1u); }

    // ---------------- Lookback 2 ----------------
    if (tid < k) {
        while (ld_acquire(&flagsB[tid]) == 0u) __nanosleep(40);
    }
    __syncthreads();                                        // S8
    {
        float4 aq = make_float4(0.f, 0.f, 0.f, 0.f);
        for (int j = w; j < k; j += NW) {
            add4(aq, g_aggq[(bN + j) * LNS + l]);
        }
        s_a[w][l] = aq;
    }
    __syncthreads();                                        // S9
    #pragma unroll
    for (int j = 0; j < NW; ++j) add4(exq, s_a[j][l]);
    // exq now = exact exclusive Ssq seed

    // ---------------- Phase 3: outputs (regs only, one store pass) ----------
    sx = exx; sn = exn;
    float4 ssq = exq;
    #pragma unroll
    for (int t = 0; t < HT; ++t) {
        float4 xv = xr[t];
        float4 o;
        P3_STEP(x, 4 * t)
        P3_STEP(y, 4 * t + 1)
        P3_STEP(z, 4 * t + 2)
        P3_STEP(w, 4 * t + 3)
        po[t * 32] = o;
    }
}

// ---------------- launch ----------------
extern "C" void kernel_launch(void* const* d_in, const int* in_sizes, int n_in,
                              void* d_out, int out_size)
{
    const float* x    = (const float*)d_in[0];
    const float* mask = (const float*)d_in[1];
    float* out        = (float*)d_out;

    revin_init_flags<<<(2 * Bn * NCH + 511) / 512, 512>>>();
    dim3 grid(NCH, Bn);
    revin_kernel<<<grid, 256>>>(x, mask, out);
}

// round 8
// speedup vs baseline: 1.1627x; 1.1627x over previous
#include <cuda_runtime.h>
#include <cstdint>

// Problem shape (fixed)
#define Bn   16
#define Tn   8192
#define Cn   128
#define NCH  128           // chunks along T
#define CT   64            // timesteps per chunk
#define NQ   4             // time-quarters per chunk
#define HT   16            // timesteps per quarter
#define LNS  32            // lanes per quarter; lane owns 4 channels (float4)

// ---------------- device scratch (static; no allocations) ----------------
__device__ float4 g_aggx[Bn * NCH * LNS];   // per-chunk local sum of x
__device__ float4 g_aggn[Bn * NCH * LNS];   // per-chunk local observed count
__device__ float4 g_aggq[Bn * NCH * LNS];   // per-chunk local sum of term^2
__device__ unsigned g_flags[2 * Bn * NCH];

// ---------------- helpers ----------------
__device__ __forceinline__ unsigned ld_acquire(const unsigned* p) {
    unsigned v;
    asm volatile("ld.acquire.gpu.u32 %0, [%1];" : "=r"(v) : "l"(p) : "memory");
    return v;
}
__device__ __forceinline__ void st_release(unsigned* p, unsigned v) {
    asm volatile("st.release.gpu.u32 [%0], %1;" :: "l"(p), "r"(v) : "memory");
}
__device__ __forceinline__ float frcp(float x) {
    float r; asm("rcp.approx.ftz.f32 %0, %1;" : "=f"(r) : "f"(x)); return r;
}
__device__ __forceinline__ float frsq(float x) {
    float r; asm("rsqrt.approx.ftz.f32 %0, %1;" : "=f"(r) : "f"(x)); return r;
}
__device__ __forceinline__ void add4(float4& a, const float4& b) {
    a.x += b.x; a.y += b.y; a.z += b.z; a.w += b.w;
}

__global__ void revin_init_flags() {
    int i = blockIdx.x * blockDim.x + threadIdx.x;
    if (i < 2 * Bn * NCH) g_flags[i] = 0u;
}

// One channel's step for P2 (accumulate lsq). mreg bit = 4*(t&7)+c of m0/m1.
#define P2_STEP(F, MR, BIT)                                          \
    {                                                                \
        float nm = (float)(((MR) >> (BIT)) & 1u);                    \
        sx.F += xv.F; sn.F += nm;                                    \
        float nn = (sn.F == 0.f) ? 1.f : sn.F;                       \
        float mean = sx.F * frcp(nn);                                \
        float d = (xv.F - mean) * nm;                                \
        lsq.F = fmaf(d, d, lsq.F);                                   \
    }

// One channel's step for P3 (produce output)
#define P3_STEP(F, MR, BIT)                                          \
    {                                                                \
        float nm = (float)(((MR) >> (BIT)) & 1u);                    \
        sx.F += xv.F; sn.F += nm;                                    \
        float nn = (sn.F == 0.f) ? 1.f : sn.F;                       \
        float rcpn = frcp(nn);                                       \
        float mean = sx.F * rcpn;                                    \
        float d = (xv.F - mean) * nm;                                \
        ssq.F = fmaf(d, d, ssq.F);                                   \
        float var = ssq.F * rcpn;                                    \
        float inv = (var > 1e-10f) ? frsq(var) : 1.f;                \
        float ov = (xv.F - mean) * inv;                              \
        o.F = fminf(fmaxf(ov, -100.f), 100.f);                       \
    }

// ---------------- main kernel ----------------
// grid = (NCH, Bn), block = 128 threads (4 quarters x 32 lanes).
__global__ __launch_bounds__(128) void revin_kernel(
    const float* __restrict__ x,
    const float* __restrict__ mask,
    float* __restrict__ out)
{
    __shared__ float4 s_a[NQ][LNS];
    __shared__ float4 s_b[NQ][LNS];

    const int tid = threadIdx.x;
    const int h = tid >> 5;          // time quarter 0..3
    const int l = tid & 31;          // channel quad
    const int k = blockIdx.x;        // chunk along T
    const int b = blockIdx.y;        // batch
    const int bN = b * NCH;

    const size_t base = (size_t)((b * Tn + k * CT + h * HT) * Cn) + 4 * l;
    const float4* __restrict__ px = (const float4*)(x    + base);
    const float4* __restrict__ pm = (const float4*)(mask + base);
    float4*       __restrict__ po = (float4*)(out + base);
    // per-timestep stride = Cn/4 = 32 float4

    unsigned* flagsA = g_flags + bN;
    unsigned* flagsB = g_flags + Bn * NCH + bN;
    const int ai = (bN + k) * LNS + l;

    // ---------------- Phase 1: local sum of x; mask -> bits ----------------
    float4 Lx = make_float4(0.f, 0.f, 0.f, 0.f);
    unsigned m0 = 0u, m1 = 0u;   // bit 4*(t mod 8)+c => observed
    #pragma unroll
    for (int t = 0; t < HT; ++t) {
        float4 xv = px[t * 32];
        float4 mv = pm[t * 32];
        add4(Lx, xv);
        unsigned bits = ((unsigned)(mv.x == 0.f))
                      | ((unsigned)(mv.y == 0.f) << 1)
                      | ((unsigned)(mv.z == 0.f) << 2)
                      | ((unsigned)(mv.w == 0.f) << 3);
        if (t < 8) m0 |= bits << (4 * t);
        else       m1 |= bits << (4 * (t - 8));
    }
    unsigned mall0 = m0, mall1 = m1;
    float4 Ln = make_float4(
        (float)(__popc(mall0 & 0x11111111u) + __popc(mall1 & 0x11111111u)),
        (float)(__popc(mall0 & 0x22222222u) + __popc(mall1 & 0x22222222u)),
        (float)(__popc(mall0 & 0x44444444u) + __popc(mall1 & 0x44444444u)),
        (float)(__popc(mall0 & 0x88888888u) + __popc(mall1 & 0x88888888u)));

    // intra-block exclusive scan over the 4 quarters
    s_a[h][l] = Lx;
    s_b[h][l] = Ln;
    __syncthreads();
    float4 exx = make_float4(0.f, 0.f, 0.f, 0.f);
    float4 exn = make_float4(0.f, 0.f, 0.f, 0.f);
    #pragma unroll
    for (int j = 0; j < NQ; ++j) {
        if (j < h) { add4(exx, s_a[j][l]); add4(exn, s_b[j][l]); }
    }
    if (h == NQ - 1) {   // last quarter writes chunk total
        float4 tx = exx, tn = exn;
        add4(tx, Lx); add4(tn, Ln);
        g_aggx[ai] = tx;
        g_aggn[ai] = tn;
    }
    __syncthreads();
    if (tid == 0) { __threadfence(); st_release(&flagsA[k], 1u); }

    // ---------------- Lookback 1: parallel wait, quarter-strided sum -------
    if (tid < k) {
        while (ld_acquire(&flagsA[tid]) == 0u) __nanosleep(40);
    }
    __syncthreads();
    {
        float4 ax = make_float4(0.f, 0.f, 0.f, 0.f);
        float4 an = make_float4(0.f, 0.f, 0.f, 0.f);
        for (int j = h; j < k; j += NQ) {
            add4(ax, g_aggx[(bN + j) * LNS + l]);
            add4(an, g_aggn[(bN + j) * LNS + l]);
        }
        s_a[h][l] = ax;
        s_b[h][l] = an;
    }
    __syncthreads();
    #pragma unroll
    for (int j = 0; j < NQ; ++j) { add4(exx, s_a[j][l]); add4(exn, s_b[j][l]); }
    // exx/exn = exact exclusive (Sx, Sn) seed for this quarter

    // ---------------- Phase 2: running mean; local term^2 ------------------
    float4 sx = exx, sn = exn;
    float4 lsq = make_float4(0.f, 0.f, 0.f, 0.f);
    #pragma unroll
    for (int t = 0; t < HT; ++t) {
        float4 xv = px[t * 32];
        if (t < 8) {
            P2_STEP(x, m0, 4 * t)
            P2_STEP(y, m0, 4 * t + 1)
            P2_STEP(z, m0, 4 * t + 2)
            P2_STEP(w, m0, 4 * t + 3)
        } else {
            P2_STEP(x, m1, 4 * (t - 8))
            P2_STEP(y, m1, 4 * (t - 8) + 1)
            P2_STEP(z, m1, 4 * (t - 8) + 2)
            P2_STEP(w, m1, 4 * (t - 8) + 3)
        }
    }

    __syncthreads();
    s_a[h][l] = lsq;
    __syncthreads();
    float4 exq = make_float4(0.f, 0.f, 0.f, 0.f);
    #pragma unroll
    for (int j = 0; j < NQ; ++j) {
        if (j < h) add4(exq, s_a[j][l]);
    }
    if (h == NQ - 1) {
        float4 tq = exq; add4(tq, lsq);
        g_aggq[ai] = tq;
    }
    __syncthreads();
    if (tid == 0) { __threadfence(); st_release(&flagsB[k], 1u); }

    // ---------------- Lookback 2 ----------------
    if (tid < k) {
        while (ld_acquire(&flagsB[tid]) == 0u) __nanosleep(40);
    }
    __syncthreads();
    {
        float4 aq = make_float4(0.f, 0.f, 0.f, 0.f);
        for (int j = h; j < k; j += NQ) {
            add4(aq, g_aggq[(bN + j) * LNS + l]);
        }
        s_a[h][l] = aq;
    }
    __syncthreads();
    #pragma unroll
    for (int j = 0; j < NQ; ++j) add4(exq, s_a[j][l]);
    // exq = exact exclusive Ssq seed

    // ---------------- Phase 3: output ----------------
    sx = exx; sn = exn;
    float4 ssq = exq;
    #pragma unroll
    for (int t = 0; t < HT; ++t) {
        float4 xv = px[t * 32];
        float4 o;
        if (t < 8) {
            P3_STEP(x, m0, 4 * t)
            P3_STEP(y, m0, 4 * t + 1)
            P3_STEP(z, m0, 4 * t + 2)
            P3_STEP(w, m0, 4 * t + 3)
        } else {
            P3_STEP(x, m1, 4 * (t - 8))
            P3_STEP(y, m1, 4 * (t - 8) + 1)
            P3_STEP(z, m1, 4 * (t - 8) + 2)
            P3_STEP(w, m1, 4 * (t - 8) + 3)
        }
        po[t * 32] = o;
    }
}

// ---------------- launch ----------------
extern "C" void kernel_launch(void* const* d_in, const int* in_sizes, int n_in,
                              void* d_out, int out_size)
{
    const float* x    = (const float*)d_in[0];
    const float* mask = (const float*)d_in[1];
    float* out        = (float*)d_out;

    revin_init_flags<<<(2 * Bn * NCH + 511) / 512, 512>>>();
    dim3 grid(NCH, Bn);
    revin_kernel<<<grid, 128>>>(x, mask, out);
}

// round 9
// speedup vs baseline: 1.3435x; 1.1555x over previous
#include <cuda_runtime.h>
#include <cstdint>

// Problem shape (fixed)
#define Bn   16
#define Tn   8192
#define Cn   128
#define NCH  128           // chunks along T
#define CT   64            // timesteps per chunk
#define NQ   4             // time-quarters per chunk
#define HT   16            // timesteps per quarter
#define HC   64            // float2 lanes per quarter (2 channels/thread)

// ---------------- device scratch (static; no allocations) ----------------
__device__ float2 g_aggx[Bn * NCH * HC];   // per-chunk local sum of x
__device__ float2 g_aggn[Bn * NCH * HC];   // per-chunk local observed count
__device__ float2 g_aggq[Bn * NCH * HC];   // per-chunk local sum of term^2
__device__ unsigned g_flags[2 * Bn * NCH];

// ---------------- helpers ----------------
__device__ __forceinline__ unsigned ld_acquire(const unsigned* p) {
    unsigned v;
    asm volatile("ld.acquire.gpu.u32 %0, [%1];" : "=r"(v) : "l"(p) : "memory");
    return v;
}
__device__ __forceinline__ void st_release(unsigned* p, unsigned v) {
    asm volatile("st.release.gpu.u32 [%0], %1;" :: "l"(p), "r"(v) : "memory");
}
__device__ __forceinline__ float frcp(float x) {
    float r; asm("rcp.approx.ftz.f32 %0, %1;" : "=f"(r) : "f"(x)); return r;
}
__device__ __forceinline__ float frsq(float x) {
    float r; asm("rsqrt.approx.ftz.f32 %0, %1;" : "=f"(r) : "f"(x)); return r;
}
__device__ __forceinline__ void add2(float2& a, const float2& b) {
    a.x += b.x; a.y += b.y;
}

__global__ void revin_init_flags() {
    int i = blockIdx.x * blockDim.x + threadIdx.x;
    if (i < 2 * Bn * NCH) g_flags[i] = 0u;
}

// ---------------- main kernel ----------------
// grid = (NCH, Bn), block = 256 threads (4 quarters x 64 float2 lanes).
// h = tid>>6 selects time quarter; l = tid&63 owns channels (2l, 2l+1).
__global__ __launch_bounds__(256) void revin_kernel(
    const float* __restrict__ x,
    const float* __restrict__ mask,
    float* __restrict__ out)
{
    __shared__ float2 s_a[NQ][HC];
    __shared__ float2 s_b[NQ][HC];

    const int tid = threadIdx.x;
    const int h = tid >> 6;          // time quarter 0..3
    const int l = tid & 63;          // channel pair
    const int k = blockIdx.x;        // chunk along T
    const int b = blockIdx.y;        // batch
    const int bN = b * NCH;

    const size_t base = (size_t)((b * Tn + k * CT + h * HT) * Cn) + 2 * l;
    const float2* __restrict__ px = (const float2*)(x    + base);
    const float2* __restrict__ pm = (const float2*)(mask + base);
    float2*       __restrict__ po = (float2*)(out + base);
    // per-timestep stride in float2 units = Cn/2 = 64

    unsigned* flagsA = g_flags + bN;
    unsigned* flagsB = g_flags + Bn * NCH + bN;
    const int ai = (bN + k) * HC + l;

    // ---------------- Phase 1: local sum of x; mask -> interleaved bits ----
    float2 Lx = make_float2(0.f, 0.f);
    unsigned m = 0u;   // bit(2t)=chA observed, bit(2t+1)=chB observed
    #pragma unroll 8
    for (int t = 0; t < HT; ++t) {
        float2 xv = px[t * 64];
        float2 mv = pm[t * 64];
        Lx.x += xv.x; Lx.y += xv.y;
        m |= ((unsigned)(mv.x == 0.f)) << (2 * t);
        m |= ((unsigned)(mv.y == 0.f)) << (2 * t + 1);
    }
    float2 Ln = make_float2((float)__popc(m & 0x55555555u),
                            (float)__popc(m & 0xAAAAAAAAu));

    // intra-block exclusive scan over the 4 quarters
    s_a[h][l] = Lx;
    s_b[h][l] = Ln;
    __syncthreads();
    float2 exx = make_float2(0.f, 0.f);
    float2 exn = make_float2(0.f, 0.f);
    #pragma unroll
    for (int j = 0; j < NQ; ++j) {
        if (j < h) { add2(exx, s_a[j][l]); add2(exn, s_b[j][l]); }
    }
    if (h == NQ - 1) {   // last quarter writes chunk total
        g_aggx[ai] = make_float2(exx.x + Lx.x, exx.y + Lx.y);
        g_aggn[ai] = make_float2(exn.x + Ln.x, exn.y + Ln.y);
    }
    __syncthreads();
    if (tid == 0) { __threadfence(); st_release(&flagsA[k], 1u); }

    // ---------------- Lookback 1: parallel wait, quarter-strided sum -------
    if (tid < k) {
        while (ld_acquire(&flagsA[tid]) == 0u) __nanosleep(40);
    }
    __syncthreads();
    {
        float2 ax = make_float2(0.f, 0.f);
        float2 an = make_float2(0.f, 0.f);
        for (int j = h; j < k; j += NQ) {
            add2(ax, g_aggx[(bN + j) * HC + l]);
            add2(an, g_aggn[(bN + j) * HC + l]);
        }
        s_a[h][l] = ax;
        s_b[h][l] = an;
    }
    __syncthreads();
    #pragma unroll
    for (int j = 0; j < NQ; ++j) { add2(exx, s_a[j][l]); add2(exn, s_b[j][l]); }
    // exx/exn = exact exclusive (Sx, Sn) seed for this quarter's first step

    // ---------------- Phase 2: running mean; local term^2 ------------------
    float2 sx = exx, sn = exn;
    float2 lsq = make_float2(0.f, 0.f);
    #pragma unroll 8
    for (int t = 0; t < HT; ++t) {
        float2 xv = px[t * 64];
        float nm, nn, mean, d;

        nm = (float)((m >> (2 * t)) & 1u);
        sx.x += xv.x; sn.x += nm;
        nn = (sn.x == 0.f) ? 1.f : sn.x;
        mean = sx.x * frcp(nn);
        d = (xv.x - mean) * nm;
        lsq.x = fmaf(d, d, lsq.x);

        nm = (float)((m >> (2 * t + 1)) & 1u);
        sx.y += xv.y; sn.y += nm;
        nn = (sn.y == 0.f) ? 1.f : sn.y;
        mean = sx.y * frcp(nn);
        d = (xv.y - mean) * nm;
        lsq.y = fmaf(d, d, lsq.y);
    }

    __syncthreads();
    s_a[h][l] = lsq;
    __syncthreads();
    float2 exq = make_float2(0.f, 0.f);
    #pragma unroll
    for (int j = 0; j < NQ; ++j) {
        if (j < h) add2(exq, s_a[j][l]);
    }
    if (h == NQ - 1) {
        g_aggq[ai] = make_float2(exq.x + lsq.x, exq.y + lsq.y);
    }
    __syncthreads();
    if (tid == 0) { __threadfence(); st_release(&flagsB[k], 1u); }

    // ---------------- Lookback 2 ----------------
    if (tid < k) {
        while (ld_acquire(&flagsB[tid]) == 0u) __nanosleep(40);
    }
    __syncthreads();
    {
        float2 aq = make_float2(0.f, 0.f);
        for (int j = h; j < k; j += NQ) {
            add2(aq, g_aggq[(bN + j) * HC + l]);
        }
        s_a[h][l] = aq;
    }
    __syncthreads();
    #pragma unroll
    for (int j = 0; j < NQ; ++j) add2(exq, s_a[j][l]);
    // exq = exact exclusive Ssq seed

    // ---------------- Phase 3: output ----------------
    sx = exx; sn = exn;
    float2 ssq = exq;
    #pragma unroll 8
    for (int t = 0; t < HT; ++t) {
        float2 xv = px[t * 64];
        float2 o;
        float nm, nn, rcpn, mean, d, var, inv, ov;

        nm = (float)((m >> (2 * t)) & 1u);
        sx.x += xv.x; sn.x += nm;
        nn = (sn.x == 0.f) ? 1.f : sn.x;
        rcpn = frcp(nn);
        mean = sx.x * rcpn;
        d = (xv.x - mean) * nm;
        ssq.x = fmaf(d, d, ssq.x);
        var = ssq.x * rcpn;
        inv = (var > 1e-10f) ? frsq(var) : 1.f;   // std>1e-5 <=> var>1e-10
        ov = (xv.x - mean) * inv;
        o.x = fminf(fmaxf(ov, -100.f), 100.f);

        nm = (float)((m >> (2 * t + 1)) & 1u);
        sx.y += xv.y; sn.y += nm;
        nn = (sn.y == 0.f) ? 1.f : sn.y;
        rcpn = frcp(nn);
        mean = sx.y * rcpn;
        d = (xv.y - mean) * nm;
        ssq.y = fmaf(d, d, ssq.y);
        var = ssq.y * rcpn;
        inv = (var > 1e-10f) ? frsq(var) : 1.f;
        ov = (xv.y - mean) * inv;
        o.y = fminf(fmaxf(ov, -100.f), 100.f);

        po[t * 64] = o;
    }
}

// ---------------- launch ----------------
extern "C" void kernel_launch(void* const* d_in, const int* in_sizes, int n_in,
                              void* d_out, int out_size)
{
    const float* x    = (const float*)d_in[0];
    const float* mask = (const float*)d_in[1];
    float* out        = (float*)d_out;

    revin_init_flags<<<(2 * Bn * NCH + 511) / 512, 512>>>();
    dim3 grid(NCH, Bn);
    revin_kernel<<<grid, 256>>>(x, mask, out);
}

// round 10
// speedup vs baseline: 1.4284x; 1.0632x over previous
#include <cuda_runtime.h>
#include <cstdint>

// Problem shape (fixed)
#define Bn   16
#define Tn   8192
#define Cn   128
#define NCH  128           // chunks along T
#define CT   64            // timesteps per chunk
#define HT   32            // timesteps per half-chunk (one mask register per channel)
#define HC   64            // float2 lanes per half (2 channels/thread)

// ---------------- device scratch (static; no allocations) ----------------
__device__ float2 g_aggx [Bn * NCH * HC];   // per-chunk local sum of x
__device__ float2 g_aggn [Bn * NCH * HC];   // per-chunk local observed count
__device__ float2 g_aggq [Bn * NCH * HC];   // per-chunk local sum of term^2
__device__ unsigned g_flags[2 * Bn * NCH];  // [0..]=phase1, [Bn*NCH..]=phase2

// ---------------- helpers ----------------
__device__ __forceinline__ unsigned ld_acquire(const unsigned* p) {
    unsigned v;
    asm volatile("ld.acquire.gpu.u32 %0, [%1];" : "=r"(v) : "l"(p) : "memory");
    return v;
}
__device__ __forceinline__ void st_release(unsigned* p, unsigned v) {
    asm volatile("st.release.gpu.u32 [%0], %1;" :: "l"(p), "r"(v) : "memory");
}
__device__ __forceinline__ float frcp(float x) {
    float r; asm("rcp.approx.ftz.f32 %0, %1;" : "=f"(r) : "f"(x)); return r;
}
__device__ __forceinline__ float frsq(float x) {
    float r; asm("rsqrt.approx.ftz.f32 %0, %1;" : "=f"(r) : "f"(x)); return r;
}

__global__ void revin_init_flags() {
    int i = blockIdx.x * blockDim.x + threadIdx.x;
    if (i < 2 * Bn * NCH) g_flags[i] = 0u;
}

// ---------------- main kernel ----------------
// grid = (NCH, Bn), block = 128 threads.
// h = tid>>6 selects time-half; l = tid&63 owns channels (2l, 2l+1).
// x for the whole chunk is staged in smem during P1; P2/P3 never touch gmem x.
__global__ __launch_bounds__(128) void revin_kernel(
    const float* __restrict__ x,
    const float* __restrict__ mask,
    float* __restrict__ out)
{
    __shared__ float2 xs[2][HT][HC];                    // 32 KB chunk cache
    __shared__ float2 s_h0x[HC], s_h0n[HC], s_h0q[HC];  // half0 locals
    __shared__ float2 s_pa[2][HC], s_pb[2][HC];         // lookback partials

    const int tid = threadIdx.x;
    const int h = tid >> 6;
    const int l = tid & 63;
    const int k = blockIdx.x;            // chunk along T
    const int b = blockIdx.y;            // batch
    const int bN = b * NCH;

    const size_t base = (size_t)((b * Tn + k * CT + h * HT) * Cn) + 2 * l;
    const float2* __restrict__ px = (const float2*)(x    + base);
    const float2* __restrict__ pm = (const float2*)(mask + base);
    float2*       __restrict__ po = (float2*)(out + base);
    // per-timestep stride in float2 units = Cn/2 = 64

    unsigned* flagsA = g_flags + bN;
    unsigned* flagsB = g_flags + Bn * NCH + bN;
    const int ai = (bN + k) * HC + l;

    // ---------------- Phase 1: gmem read -> smem cache; local sums --------
    float2 Lx = make_float2(0.f, 0.f);
    unsigned mA = 0u, mB = 0u;       // bit t set => observed at local timestep t
    #pragma unroll 8
    for (int t = 0; t < HT; ++t) {
        float2 xv = px[t * 64];
        float2 mv = pm[t * 64];
        xs[h][t][l] = xv;            // thread-private slice: no sync needed
        Lx.x += xv.x; Lx.y += xv.y;
        mA |= (unsigned)(mv.x == 0.f) << t;
        mB |= (unsigned)(mv.y == 0.f) << t;
    }
    float2 Ln = make_float2((float)__popc(mA), (float)__popc(mB));

    if (h == 0) { s_h0x[l] = Lx; s_h0n[l] = Ln; }
    __syncthreads();
    if (h == 1) {
        float2 h0x = s_h0x[l], h0n = s_h0n[l];
        g_aggx[ai] = make_float2(h0x.x + Lx.x, h0x.y + Lx.y);
        g_aggn[ai] = make_float2(h0n.x + Ln.x, h0n.y + Ln.y);
    }
    __syncthreads();
    if (tid == 0) { __threadfence(); st_release(&flagsA[k], 1u); }

    // ---------------- Lookback 1: parallel wait, parity-split sum ----------
    if (tid < k) {
        while (ld_acquire(&flagsA[tid]) == 0u) __nanosleep(40);
    }
    __syncthreads();
    {
        float2 pxs = make_float2(0.f, 0.f), pns = make_float2(0.f, 0.f);
        #pragma unroll 4
        for (int j = h; j < k; j += 2) {
            float2 a = g_aggx[(bN + j) * HC + l];
            float2 n = g_aggn[(bN + j) * HC + l];
            pxs.x += a.x; pxs.y += a.y;
            pns.x += n.x; pns.y += n.y;
        }
        s_pa[h][l] = pxs; s_pb[h][l] = pns;
    }
    __syncthreads();

    float2 exx, exn;   // chunk-exclusive (Sx, Sn)
    {
        float2 a0 = s_pa[0][l], a1 = s_pa[1][l];
        float2 n0 = s_pb[0][l], n1 = s_pb[1][l];
        exx = make_float2(a0.x + a1.x, a0.y + a1.y);
        exn = make_float2(n0.x + n1.x, n0.y + n1.y);
    }
    // this thread's starting state (half1 adds half0's local)
    float2 ssx = exx, ssn = exn;
    if (h == 1) {
        float2 h0x = s_h0x[l], h0n = s_h0n[l];
        ssx.x += h0x.x; ssx.y += h0x.y;
        ssn.x += h0n.x; ssn.y += h0n.y;
    }

    // ---------------- Phase 2: running mean; half-local Ssq (smem only) ----
    float2 sx = ssx, sn = ssn;
    float2 lsq = make_float2(0.f, 0.f);
    #pragma unroll 8
    for (int t = 0; t < HT; ++t) {
        float2 xv = xs[h][t][l];
        float nm, nn, mean, d;

        nm = (float)((mA >> t) & 1u);
        sx.x += xv.x; sn.x += nm;
        nn = (sn.x == 0.f) ? 1.f : sn.x;
        mean = sx.x * frcp(nn);
        d = (xv.x - mean) * nm;
        lsq.x = fmaf(d, d, lsq.x);

        nm = (float)((mB >> t) & 1u);
        sx.y += xv.y; sn.y += nm;
        nn = (sn.y == 0.f) ? 1.f : sn.y;
        mean = sx.y * frcp(nn);
        d = (xv.y - mean) * nm;
        lsq.y = fmaf(d, d, lsq.y);
    }

    if (h == 0) { s_h0q[l] = lsq; }
    __syncthreads();
    if (h == 1) {
        float2 h0q = s_h0q[l];
        g_aggq[ai] = make_float2(h0q.x + lsq.x, h0q.y + lsq.y);
    }
    __syncthreads();
    if (tid == 0) { __threadfence(); st_release(&flagsB[k], 1u); }

    // ---------------- Lookback 2 ----------------
    if (tid < k) {
        while (ld_acquire(&flagsB[tid]) == 0u) __nanosleep(40);
    }
    __syncthreads();
    {
        float2 pq = make_float2(0.f, 0.f);
        #pragma unroll 4
        for (int j = h; j < k; j += 2) {
            float2 q = g_aggq[(bN + j) * HC + l];
            pq.x += q.x; pq.y += q.y;
        }
        s_pa[h][l] = pq;
    }
    __syncthreads();

    float2 ssq;
    {
        float2 q0 = s_pa[0][l], q1 = s_pa[1][l];
        ssq = make_float2(q0.x + q1.x, q0.y + q1.y);
    }
    if (h == 1) {
        float2 h0q = s_h0q[l];
        ssq.x += h0q.x; ssq.y += h0q.y;
    }

    // ---------------- Phase 3: output (smem reads, gmem stores) ------------
    sx = ssx; sn = ssn;
    #pragma unroll 8
    for (int t = 0; t < HT; ++t) {
        float2 xv = xs[h][t][l];
        float2 o;
        float nm, nn, rcpn, mean, d, var, inv, ov;

        nm = (float)((mA >> t) & 1u);
        sx.x += xv.x; sn.x += nm;
        nn = (sn.x == 0.f) ? 1.f : sn.x;
        rcpn = frcp(nn);
        mean = sx.x * rcpn;
        d = (xv.x - mean) * nm;
        ssq.x = fmaf(d, d, ssq.x);
        var = ssq.x * rcpn;
        inv = (var > 1e-10f) ? frsq(var) : 1.f;   // std>1e-5 <=> var>1e-10
        ov = (xv.x - mean) * inv;
        o.x = fminf(fmaxf(ov, -100.f), 100.f);

        nm = (float)((mB >> t) & 1u);
        sx.y += xv.y; sn.y += nm;
        nn = (sn.y == 0.f) ? 1.f : sn.y;
        rcpn = frcp(nn);
        mean = sx.y * rcpn;
        d = (xv.y - mean) * nm;
        ssq.y = fmaf(d, d, ssq.y);
        var = ssq.y * rcpn;
        inv = (var > 1e-10f) ? frsq(var) : 1.f;
        ov = (xv.y - mean) * inv;
        o.y = fminf(fmaxf(ov, -100.f), 100.f);

        po[t * 64] = o;
    }
}

// ---------------- launch ----------------
extern "C" void kernel_launch(void* const* d_in, const int* in_sizes, int n_in,
                              void* d_out, int out_size)
{
    const float* x    = (const float*)d_in[0];
    const float* mask = (const float*)d_in[1];
    float* out        = (float*)d_out;

    revin_init_flags<<<(2 * Bn * NCH + 511) / 512, 512>>>();
    dim3 grid(NCH, Bn);
    revin_kernel<<<grid, 128>>>(x, mask, out);
}